// round 4
// baseline (speedup 1.0000x reference)
#include <cuda_runtime.h>
#include <math.h>
#include <stdint.h>

#define CH     512
#define NPIX   4096
#define BATCH  4
#define GROUPS 32

#define PELEM  ((size_t)BATCH * NPIX * CH)        // 8388608
#define SELEM  ((size_t)BATCH * NPIX * NPIX)      // 67108864

// ---------------- scratch (device globals: allocation-guard safe) ----------
__device__ float g_hn[PELEM];    // hn^T [b][n][c]
__device__ float g_q [PELEM];    // q    [b][n][c]
__device__ float g_k [PELEM];    // k    [b][n][c]
__device__ float g_vt[PELEM];    // v^T  [b][c][n]
__device__ float g_o [PELEM];    // O    [b][n][c]
__device__ float g_S [SELEM];    // S / probs [b][n][m]
__device__ float g_mean[BATCH * GROUPS];
__device__ float g_rstd[BATCH * GROUPS];

// ---------------- GroupNorm ------------------------------------------------
__global__ void gn_stats(const float* __restrict__ x) {
    int bg = blockIdx.x;   // b*32+g; group = 16 contiguous channels
    const float4* p = (const float4*)(x + (long long)bg * 16 * NPIX);
    float s = 0.f, sq = 0.f;
    for (int i = threadIdx.x; i < 16 * NPIX / 4; i += blockDim.x) {
        float4 v = p[i];
        s  += v.x + v.y + v.z + v.w;
        sq += v.x*v.x + v.y*v.y + v.z*v.z + v.w*v.w;
    }
    __shared__ float sh_s[8], sh_q[8];
    #pragma unroll
    for (int o = 16; o; o >>= 1) {
        s  += __shfl_xor_sync(0xffffffffu, s,  o);
        sq += __shfl_xor_sync(0xffffffffu, sq, o);
    }
    if ((threadIdx.x & 31) == 0) { sh_s[threadIdx.x >> 5] = s; sh_q[threadIdx.x >> 5] = sq; }
    __syncthreads();
    if (threadIdx.x == 0) {
        float ts = 0.f, tq = 0.f;
        #pragma unroll
        for (int i = 0; i < 8; i++) { ts += sh_s[i]; tq += sh_q[i]; }
        const float inv = 1.f / (float)(16 * NPIX);
        float m   = ts * inv;
        float var = tq * inv - m * m;
        g_mean[bg] = m;
        g_rstd[bg] = rsqrtf(var + 1e-6f);
    }
}

// GroupNorm apply + transpose: x[b][c][n] -> hnT[b][n][c]
__global__ void gn_apply_t(const float* __restrict__ x,
                           const float* __restrict__ gamma,
                           const float* __restrict__ beta) {
    __shared__ float tile[32][33];
    int b = blockIdx.z, c0 = blockIdx.y * 32, n0 = blockIdx.x * 32;
    int tx = threadIdx.x, ty = threadIdx.y;   // (32, 8)
    const float* xb = x + ((long long)b * CH + c0) * NPIX;
    #pragma unroll
    for (int i = 0; i < 4; i++)
        tile[ty + 8*i][tx] = xb[(long long)(ty + 8*i) * NPIX + n0 + tx];
    __syncthreads();
    int c  = c0 + tx;
    int bg = b * GROUPS + (c >> 4);
    float ga = gamma[c] * g_rstd[bg];
    float be = beta[c] - g_mean[bg] * ga;
    #pragma unroll
    for (int i = 0; i < 4; i++) {
        int n = n0 + ty + 8*i;
        g_hn[((long long)b * NPIX + n) * CH + c] = tile[tx][ty + 8*i] * ga + be;
    }
}

// ---------------- tf32 tensor-core GEMM (both operands K-contiguous) -------
// C[m][n] = alpha * sum_k A[m][k]*B[n][k] (+bias) (+resid)
// Fragment-packed smem:
//   A: [buf][(kb*8+mb)*128 + perm(lane)*4 + j]  (vectorized LDS.128 frag reads)
//   B: [buf][(kb*16+nb)*64 + perm(lane)*2 + j]  (vectorized LDS.64)
// perm(lane) = (lane&3)*8 + (lane>>2)

__device__ __forceinline__ float f2tf(float x) {
    uint32_t r;
    asm("cvt.rna.tf32.f32 %0, %1;" : "=r"(r) : "f"(x));
    return __uint_as_float(r);
}

__device__ __forceinline__ void mma_tf32(float* d, const uint32_t* a, const uint32_t* b) {
    asm volatile(
        "mma.sync.aligned.m16n8k8.row.col.f32.tf32.tf32.f32 "
        "{%0,%1,%2,%3}, {%4,%5,%6,%7}, {%8,%9}, {%0,%1,%2,%3};\n"
        : "+f"(d[0]), "+f"(d[1]), "+f"(d[2]), "+f"(d[3])
        : "r"(a[0]), "r"(a[1]), "r"(a[2]), "r"(a[3]), "r"(b[0]), "r"(b[1]));
}

__global__ void __launch_bounds__(256, 2)
gemm_tf32(const float* __restrict__ Ag, const float* __restrict__ Bg,
          float* __restrict__ Cg,
          int K, int lda, int ldb, int ldc,
          long long sA, long long sB, long long sC,
          float alpha, const float* __restrict__ bias, int bmode,
          const float* __restrict__ resid, long long sR)
{
    __shared__ float As[2][2048];
    __shared__ float Bs[2][2048];

    const int t = threadIdx.x, lane = t & 31, warp = t >> 5;
    const int wm = warp >> 2, wn = warp & 3;        // 2 x 4 warp grid
    const int fr = lane >> 2, fc = lane & 3;
    const int bi = blockIdx.y * 128, bn = blockIdx.x * 128, bz = blockIdx.z;

    const float* A = Ag + bz * sA;
    const float* B = Bg + bz * sB;

    // global load geometry: idx = t + 256*i -> row = (t>>2)+64*i, quad = t&3
    const int lrow = t >> 2, lq = t & 3;
    const int kb = lq >> 1, chi = lq & 1;
    int S0a[2], S0b[2];
    #pragma unroll
    for (int i = 0; i < 2; i++) {
        int rm = lrow + 64 * i;
        S0a[i] = (kb * 8 + (rm >> 4)) * 128 + (rm & 7) * 4 + ((rm >> 3) & 1) + 2 * chi;
        S0b[i] = (kb * 16 + (rm >> 3)) * 64 + (rm & 7) * 2 + chi;
    }

    float acc[4][4][4];
    #pragma unroll
    for (int mi = 0; mi < 4; mi++)
        #pragma unroll
        for (int ni = 0; ni < 4; ni++)
            #pragma unroll
            for (int q = 0; q < 4; q++) acc[mi][ni][q] = 0.f;

    const int nk = K >> 4;
    float4 fa[2], fb[2];

    auto LOAD = [&](int ch) {
        const int k0 = ch << 4;
        #pragma unroll
        for (int i = 0; i < 2; i++) {
            fa[i] = *(const float4*)(A + (long long)(bi + lrow + 64*i) * lda + k0 + 4*lq);
            fb[i] = *(const float4*)(B + (long long)(bn + lrow + 64*i) * ldb + k0 + 4*lq);
        }
    };
    auto STORE = [&](int buf) {
        #pragma unroll
        for (int i = 0; i < 2; i++) {
            As[buf][S0a[i] +  0] = f2tf(fa[i].x);
            As[buf][S0a[i] + 32] = f2tf(fa[i].y);
            As[buf][S0a[i] + 64] = f2tf(fa[i].z);
            As[buf][S0a[i] + 96] = f2tf(fa[i].w);
            Bs[buf][S0b[i] +  0] = f2tf(fb[i].x);
            Bs[buf][S0b[i] + 16] = f2tf(fb[i].y);
            Bs[buf][S0b[i] + 32] = f2tf(fb[i].z);
            Bs[buf][S0b[i] + 48] = f2tf(fb[i].w);
        }
    };
    auto COMPUTE = [&](int buf) {
        #pragma unroll
        for (int s = 0; s < 2; s++) {
            float4 af[4];
            float2 bf2[4];
            #pragma unroll
            for (int mi = 0; mi < 4; mi++)
                af[mi] = *(const float4*)&As[buf][(s*8 + wm*4 + mi)*128 + (fc*8 + fr)*4];
            #pragma unroll
            for (int ni = 0; ni < 4; ni++)
                bf2[ni] = *(const float2*)&Bs[buf][(s*16 + wn*4 + ni)*64 + (fc*8 + fr)*2];
            #pragma unroll
            for (int mi = 0; mi < 4; mi++)
                #pragma unroll
                for (int ni = 0; ni < 4; ni++)
                    mma_tf32(acc[mi][ni], (const uint32_t*)&af[mi], (const uint32_t*)&bf2[ni]);
        }
    };

    LOAD(0);
    STORE(0);
    __syncthreads();
    for (int ch = 0; ch < nk; ch++) {
        const int buf = ch & 1;
        if (ch + 1 < nk) LOAD(ch + 1);
        COMPUTE(buf);
        if (ch + 1 < nk) {
            STORE(1 - buf);
            __syncthreads();
        }
    }

    // -------- epilogue -----------------------------------------------------
    float* C = Cg + bz * sC;
    #pragma unroll
    for (int mi = 0; mi < 4; mi++) {
        int row = bi + wm * 64 + mi * 16 + fr;
        float bv0 = 0.f, bv1 = 0.f;
        if (bmode == 1) { bv0 = bias[row]; bv1 = bias[row + 8]; }
        #pragma unroll
        for (int ni = 0; ni < 4; ni++) {
            int col = bn + wn * 32 + ni * 8 + 2 * fc;
            float2 o0, o1;
            o0.x = acc[mi][ni][0] * alpha; o0.y = acc[mi][ni][1] * alpha;
            o1.x = acc[mi][ni][2] * alpha; o1.y = acc[mi][ni][3] * alpha;
            if (bmode == 1) {
                o0.x += bv0; o0.y += bv0; o1.x += bv1; o1.y += bv1;
            } else if (bmode == 2) {
                float2 bb = *(const float2*)(bias + col);
                o0.x += bb.x; o0.y += bb.y; o1.x += bb.x; o1.y += bb.y;
            }
            if (resid) {
                const float* R = resid + bz * sR;
                float2 r0 = *(const float2*)(R + (long long)row * ldc + col);
                float2 r1 = *(const float2*)(R + (long long)(row + 8) * ldc + col);
                o0.x += r0.x; o0.y += r0.y; o1.x += r1.x; o1.y += r1.y;
            }
            *(float2*)(C + (long long)row * ldc + col)       = o0;
            *(float2*)(C + (long long)(row + 8) * ldc + col) = o1;
        }
    }
}

// ---------------- row softmax (4096 per row, fp32 in place) ----------------
__global__ void softmax_rows(float* __restrict__ S) {
    float* p = S + (long long)blockIdx.x * NPIX;
    const int t = threadIdx.x;
    float4 v[4];
    float mx = -1e30f;
    #pragma unroll
    for (int j = 0; j < 4; j++) {
        v[j] = ((const float4*)p)[t + j * 256];
        mx = fmaxf(mx, fmaxf(fmaxf(v[j].x, v[j].y), fmaxf(v[j].z, v[j].w)));
    }
    __shared__ float shm[8], shs[8];
    #pragma unroll
    for (int o = 16; o; o >>= 1) mx = fmaxf(mx, __shfl_xor_sync(0xffffffffu, mx, o));
    if ((t & 31) == 0) shm[t >> 5] = mx;
    __syncthreads();
    mx = shm[0];
    #pragma unroll
    for (int i = 1; i < 8; i++) mx = fmaxf(mx, shm[i]);

    float s = 0.f;
    #pragma unroll
    for (int j = 0; j < 4; j++) {
        v[j].x = __expf(v[j].x - mx); v[j].y = __expf(v[j].y - mx);
        v[j].z = __expf(v[j].z - mx); v[j].w = __expf(v[j].w - mx);
        s += v[j].x + v[j].y + v[j].z + v[j].w;
    }
    #pragma unroll
    for (int o = 16; o; o >>= 1) s += __shfl_xor_sync(0xffffffffu, s, o);
    if ((t & 31) == 0) shs[t >> 5] = s;
    __syncthreads();
    s = 0.f;
    #pragma unroll
    for (int i = 0; i < 8; i++) s += shs[i];
    float inv = 1.f / s;
    #pragma unroll
    for (int j = 0; j < 4; j++) {
        v[j].x *= inv; v[j].y *= inv; v[j].z *= inv; v[j].w *= inv;
        ((float4*)p)[t + j * 256] = v[j];
    }
}

// ---------------- launch ---------------------------------------------------
extern "C" void kernel_launch(void* const* d_in, const int* in_sizes, int n_in,
                              void* d_out, int out_size) {
    const float* x     = (const float*)d_in[0];
    const float* gamma = (const float*)d_in[1];
    const float* beta  = (const float*)d_in[2];
    const float* wq    = (const float*)d_in[3];
    const float* bq    = (const float*)d_in[4];
    const float* wk    = (const float*)d_in[5];
    const float* bk    = (const float*)d_in[6];
    const float* wv    = (const float*)d_in[7];
    const float* bv    = (const float*)d_in[8];
    const float* wo    = (const float*)d_in[9];
    const float* bo    = (const float*)d_in[10];
    float* out = (float*)d_out;

    float *hn, *q, *k, *vt, *o, *S;
    cudaGetSymbolAddress((void**)&hn, g_hn);
    cudaGetSymbolAddress((void**)&q,  g_q);
    cudaGetSymbolAddress((void**)&k,  g_k);
    cudaGetSymbolAddress((void**)&vt, g_vt);
    cudaGetSymbolAddress((void**)&o,  g_o);
    cudaGetSymbolAddress((void**)&S,  g_S);

    const long long P  = (long long)CH * NPIX;     // 2097152
    const long long PS = (long long)NPIX * NPIX;   // 16777216
    const float scale  = 0.044194173824159216f;    // 512^-0.5

    gn_stats<<<BATCH * GROUPS, 256>>>(x);
    gn_apply_t<<<dim3(NPIX / 32, CH / 32, BATCH), dim3(32, 8)>>>(x, gamma, beta);

    // q[n][c] = hnT[n][:] . Wq[c][:] + bq[c]   (M=4096, N=512, K=512)
    gemm_tf32<<<dim3(4, 32, BATCH), 256>>>(
        hn, wq, q, CH, CH, CH, CH, P, 0, P, 1.f, bq, 2, nullptr, 0);
    gemm_tf32<<<dim3(4, 32, BATCH), 256>>>(
        hn, wk, k, CH, CH, CH, CH, P, 0, P, 1.f, bk, 2, nullptr, 0);
    // vT[c][n] = Wv[c][:] . hnT[n][:] + bv[c]  (M=512, N=4096, K=512)
    gemm_tf32<<<dim3(32, 4, BATCH), 256>>>(
        wv, hn, vt, CH, CH, CH, NPIX, 0, P, P, 1.f, bv, 1, nullptr, 0);

    // S[i][j] = scale * q[i][:] . k[j][:]      (M=N=4096, K=512)
    gemm_tf32<<<dim3(32, 32, BATCH), 256>>>(
        q, k, S, CH, CH, CH, NPIX, P, P, PS, scale, nullptr, 0, nullptr, 0);

    softmax_rows<<<BATCH * NPIX, 256>>>(S);

    // O[i][c] = P[i][:] . vT[c][:]             (M=4096, N=512, K=4096)
    gemm_tf32<<<dim3(4, 32, BATCH), 256>>>(
        S, vt, o, NPIX, NPIX, NPIX, CH, PS, P, P, 1.f, nullptr, 0, nullptr, 0);

    // out[c][n] = Wo[c][:] . O[n][:] + bo[c] + x[c][n]  (M=512, N=4096, K=512)
    gemm_tf32<<<dim3(32, 4, BATCH), 256>>>(
        wo, o, out, CH, CH, CH, NPIX, 0, P, P, 1.f, bo, 1, x, P);
}

// round 5
// speedup vs baseline: 2.1224x; 2.1224x over previous
#include <cuda_runtime.h>
#include <math.h>
#include <stdint.h>

#define CH     512
#define NPIX   4096
#define BATCH  4
#define GROUPS 32
#define STAGES 4

#define PELEM  ((size_t)BATCH * NPIX * CH)        // 8388608
#define SELEM  ((size_t)BATCH * NPIX * NPIX)      // 67108864

// ---------------- scratch (device globals: allocation-guard safe) ----------
__device__ float g_hn[PELEM];    // hn^T [b][n][c]  (tf32-rounded)
__device__ float g_q [PELEM];    // q    [b][n][c]  (tf32)
__device__ float g_k [PELEM];    // k    [b][n][c]  (tf32)
__device__ float g_vt[PELEM];    // v^T  [b][c][n]  (tf32)
__device__ float g_o [PELEM];    // O    [b][n][c]  (tf32)
__device__ float g_S [SELEM];    // S logits fp32 / probs tf32
__device__ float g_w [4 * CH * CH];  // tf32 copies of wq,wk,wv,wo
__device__ float g_mean[BATCH * GROUPS];
__device__ float g_rstd[BATCH * GROUPS];

// ---------------- helpers ---------------------------------------------------
__device__ __forceinline__ float f2tf(float x) {
    uint32_t r;
    asm("cvt.rna.tf32.f32 %0, %1;" : "=r"(r) : "f"(x));
    return __uint_as_float(r);
}
__device__ __forceinline__ uint32_t smem_u32(const void* p) {
    uint32_t a;
    asm("{ .reg .u64 t; cvta.to.shared.u64 t, %1; cvt.u32.u64 %0, t; }"
        : "=r"(a) : "l"(p));
    return a;
}
__device__ __forceinline__ void cp16(uint32_t dst, const float* src) {
    asm volatile("cp.async.cg.shared.global [%0], [%1], 16;" :: "r"(dst), "l"(src));
}
__device__ __forceinline__ void mma_tf32(float* d, const uint32_t* a, const uint32_t* b) {
    asm volatile(
        "mma.sync.aligned.m16n8k8.row.col.f32.tf32.tf32.f32 "
        "{%0,%1,%2,%3}, {%4,%5,%6,%7}, {%8,%9}, {%0,%1,%2,%3};\n"
        : "+f"(d[0]), "+f"(d[1]), "+f"(d[2]), "+f"(d[3])
        : "r"(a[0]), "r"(a[1]), "r"(a[2]), "r"(a[3]), "r"(b[0]), "r"(b[1]));
}

// ---------------- GroupNorm ------------------------------------------------
__global__ void gn_stats(const float* __restrict__ x) {
    int bg = blockIdx.x;   // b*32+g; group = 16 contiguous channels
    const float4* p = (const float4*)(x + (long long)bg * 16 * NPIX);
    float s = 0.f, sq = 0.f;
    for (int i = threadIdx.x; i < 16 * NPIX / 4; i += blockDim.x) {
        float4 v = p[i];
        s  += v.x + v.y + v.z + v.w;
        sq += v.x*v.x + v.y*v.y + v.z*v.z + v.w*v.w;
    }
    __shared__ float sh_s[8], sh_q[8];
    #pragma unroll
    for (int o = 16; o; o >>= 1) {
        s  += __shfl_xor_sync(0xffffffffu, s,  o);
        sq += __shfl_xor_sync(0xffffffffu, sq, o);
    }
    if ((threadIdx.x & 31) == 0) { sh_s[threadIdx.x >> 5] = s; sh_q[threadIdx.x >> 5] = sq; }
    __syncthreads();
    if (threadIdx.x == 0) {
        float ts = 0.f, tq = 0.f;
        #pragma unroll
        for (int i = 0; i < 8; i++) { ts += sh_s[i]; tq += sh_q[i]; }
        const float inv = 1.f / (float)(16 * NPIX);
        float m   = ts * inv;
        float var = tq * inv - m * m;
        g_mean[bg] = m;
        g_rstd[bg] = rsqrtf(var + 1e-6f);
    }
}

// GroupNorm apply + transpose + tf32 round: x[b][c][n] -> hnT[b][n][c]
__global__ void gn_apply_t(const float* __restrict__ x,
                           const float* __restrict__ gamma,
                           const float* __restrict__ beta) {
    __shared__ float tile[32][33];
    int b = blockIdx.z, c0 = blockIdx.y * 32, n0 = blockIdx.x * 32;
    int tx = threadIdx.x, ty = threadIdx.y;   // (32, 8)
    const float* xb = x + ((long long)b * CH + c0) * NPIX;
    #pragma unroll
    for (int i = 0; i < 4; i++)
        tile[ty + 8*i][tx] = xb[(long long)(ty + 8*i) * NPIX + n0 + tx];
    __syncthreads();
    int c  = c0 + tx;
    int bg = b * GROUPS + (c >> 4);
    float ga = gamma[c] * g_rstd[bg];
    float be = beta[c] - g_mean[bg] * ga;
    #pragma unroll
    for (int i = 0; i < 4; i++) {
        int n = n0 + ty + 8*i;
        g_hn[((long long)b * NPIX + n) * CH + c] = f2tf(tile[tx][ty + 8*i] * ga + be);
    }
}

// ---------------- weight tf32 copy -----------------------------------------
__global__ void cvt_w(const float* __restrict__ w, float* __restrict__ o) {
    int i = blockIdx.x * blockDim.x + threadIdx.x;
    float4 v = ((const float4*)w)[i];
    float4 r;
    r.x = f2tf(v.x); r.y = f2tf(v.y); r.z = f2tf(v.z); r.w = f2tf(v.w);
    ((float4*)o)[i] = r;
}

// ---------------- tf32 tensor-core GEMM, cp.async 4-stage pipeline ---------
// C[m][n] = alpha * sum_k A[m][k]*B[n][k] (+bias) (+resid)
// Both operands K-contiguous, already tf32-rounded.
// smem layout per stage: word(row,k) = row*16 + (((k>>2)^((row>>1)&3))*4 + (k&3))

__global__ void __launch_bounds__(256, 2)
gemm_tf32(const float* __restrict__ Ag, const float* __restrict__ Bg,
          float* __restrict__ Cg,
          int K, int lda, int ldb, int ldc,
          long long sA, long long sB, long long sC,
          float alpha, const float* __restrict__ bias, int bmode, int cvtout,
          const float* __restrict__ resid, long long sR)
{
    extern __shared__ float sm[];   // STAGES * 4096 floats (A 2048 | B 2048)
    const uint32_t smb = smem_u32(sm);

    const int t = threadIdx.x, lane = t & 31, warp = t >> 5;
    const int wm = warp >> 2, wn = warp & 3;        // 2 x 4 warp grid, 64x32 tiles
    const int fr = lane >> 2, fc = lane & 3;
    const int sw = (fr >> 1) & 3;                    // uniform swizzle phase
    const int bi = blockIdx.y * 128, bn = blockIdx.x * 128, bz = blockIdx.z;

    const float* A = Ag + bz * sA;
    const float* B = Bg + bz * sB;

    // copy geometry: idx = t + 256*i over 512 16B-chunks per operand
    const int crow0 = t >> 2, cc4 = t & 3;

    float acc[4][4][4];
    #pragma unroll
    for (int mi = 0; mi < 4; mi++)
        #pragma unroll
        for (int ni = 0; ni < 4; ni++)
            #pragma unroll
            for (int q = 0; q < 4; q++) acc[mi][ni][q] = 0.f;

    const int nk = K >> 4;

    auto ISSUE = [&](int ch, int slot) {
        const int k0 = ch << 4;
        const uint32_t sbase = smb + (uint32_t)slot * 16384u;
        #pragma unroll
        for (int i = 0; i < 2; i++) {
            int row = crow0 + 64 * i;
            int chp = cc4 ^ ((row >> 1) & 3);
            uint32_t off = (uint32_t)(row * 16 + chp * 4) * 4u;
            cp16(sbase + off,          A + (long long)(bi + row) * lda + k0 + 4 * cc4);
            cp16(sbase + 8192u + off,  B + (long long)(bn + row) * ldb + k0 + 4 * cc4);
        }
    };
    auto COMPUTE = [&](int slot) {
        const float* SA = sm + slot * 4096;
        const float* SB = sm + slot * 4096 + 2048;
        #pragma unroll
        for (int s = 0; s < 2; s++) {
            const int e0 = ((2 * s) ^ sw) << 2;     // a0/b0 chunk offset
            const int e1 = e0 ^ 4;                  // a2/b1 chunk offset
            uint32_t af[4][4], bf[4][2];
            #pragma unroll
            for (int mi = 0; mi < 4; mi++) {
                int base = (wm * 64 + mi * 16 + fr) * 16 + fc;
                af[mi][0] = __float_as_uint(SA[base + e0]);
                af[mi][1] = __float_as_uint(SA[base + 128 + e0]);
                af[mi][2] = __float_as_uint(SA[base + e1]);
                af[mi][3] = __float_as_uint(SA[base + 128 + e1]);
            }
            #pragma unroll
            for (int ni = 0; ni < 4; ni++) {
                int base = (wn * 32 + ni * 8 + fr) * 16 + fc;
                bf[ni][0] = __float_as_uint(SB[base + e0]);
                bf[ni][1] = __float_as_uint(SB[base + e1]);
            }
            #pragma unroll
            for (int mi = 0; mi < 4; mi++)
                #pragma unroll
                for (int ni = 0; ni < 4; ni++)
                    mma_tf32(acc[mi][ni], af[mi], bf[ni]);
        }
    };

    // prologue: fill STAGES-1 stages
    #pragma unroll
    for (int p = 0; p < STAGES - 1; p++) {
        ISSUE(p, p);
        asm volatile("cp.async.commit_group;" ::: "memory");
    }

    for (int ch = 0; ch < nk; ch++) {
        asm volatile("cp.async.wait_group %0;" :: "n"(STAGES - 2) : "memory");
        __syncthreads();
        if (ch + STAGES - 1 < nk) ISSUE(ch + STAGES - 1, (ch + STAGES - 1) & (STAGES - 1));
        asm volatile("cp.async.commit_group;" ::: "memory");
        COMPUTE(ch & (STAGES - 1));
    }

    // -------- epilogue -----------------------------------------------------
    float* C = Cg + bz * sC;
    #pragma unroll
    for (int mi = 0; mi < 4; mi++) {
        int row = bi + wm * 64 + mi * 16 + fr;
        float bv0 = 0.f, bv1 = 0.f;
        if (bmode == 1) { bv0 = bias[row]; bv1 = bias[row + 8]; }
        #pragma unroll
        for (int ni = 0; ni < 4; ni++) {
            int col = bn + wn * 32 + ni * 8 + 2 * fc;
            float2 o0, o1;
            o0.x = acc[mi][ni][0] * alpha; o0.y = acc[mi][ni][1] * alpha;
            o1.x = acc[mi][ni][2] * alpha; o1.y = acc[mi][ni][3] * alpha;
            if (bmode == 1) {
                o0.x += bv0; o0.y += bv0; o1.x += bv1; o1.y += bv1;
            } else if (bmode == 2) {
                float2 bb = *(const float2*)(bias + col);
                o0.x += bb.x; o0.y += bb.y; o1.x += bb.x; o1.y += bb.y;
            }
            if (resid) {
                const float* R = resid + bz * sR;
                float2 r0 = *(const float2*)(R + (long long)row * ldc + col);
                float2 r1 = *(const float2*)(R + (long long)(row + 8) * ldc + col);
                o0.x += r0.x; o0.y += r0.y; o1.x += r1.x; o1.y += r1.y;
            }
            if (cvtout) {
                o0.x = f2tf(o0.x); o0.y = f2tf(o0.y);
                o1.x = f2tf(o1.x); o1.y = f2tf(o1.y);
            }
            *(float2*)(C + (long long)row * ldc + col)       = o0;
            *(float2*)(C + (long long)(row + 8) * ldc + col) = o1;
        }
    }
}

// ---------------- row softmax (4096 per row; tf32-rounded output) ----------
__global__ void softmax_rows(float* __restrict__ S) {
    float* p = S + (long long)blockIdx.x * NPIX;
    const int t = threadIdx.x;
    float4 v[4];
    float mx = -1e30f;
    #pragma unroll
    for (int j = 0; j < 4; j++) {
        v[j] = ((const float4*)p)[t + j * 256];
        mx = fmaxf(mx, fmaxf(fmaxf(v[j].x, v[j].y), fmaxf(v[j].z, v[j].w)));
    }
    __shared__ float shm[8], shs[8];
    #pragma unroll
    for (int o = 16; o; o >>= 1) mx = fmaxf(mx, __shfl_xor_sync(0xffffffffu, mx, o));
    if ((t & 31) == 0) shm[t >> 5] = mx;
    __syncthreads();
    mx = shm[0];
    #pragma unroll
    for (int i = 1; i < 8; i++) mx = fmaxf(mx, shm[i]);

    float s = 0.f;
    #pragma unroll
    for (int j = 0; j < 4; j++) {
        v[j].x = __expf(v[j].x - mx); v[j].y = __expf(v[j].y - mx);
        v[j].z = __expf(v[j].z - mx); v[j].w = __expf(v[j].w - mx);
        s += v[j].x + v[j].y + v[j].z + v[j].w;
    }
    #pragma unroll
    for (int o = 16; o; o >>= 1) s += __shfl_xor_sync(0xffffffffu, s, o);
    if ((t & 31) == 0) shs[t >> 5] = s;
    __syncthreads();
    s = 0.f;
    #pragma unroll
    for (int i = 0; i < 8; i++) s += shs[i];
    float inv = 1.f / s;
    #pragma unroll
    for (int j = 0; j < 4; j++) {
        v[j].x = f2tf(v[j].x * inv); v[j].y = f2tf(v[j].y * inv);
        v[j].z = f2tf(v[j].z * inv); v[j].w = f2tf(v[j].w * inv);
        ((float4*)p)[t + j * 256] = v[j];
    }
}

// ---------------- launch ---------------------------------------------------
extern "C" void kernel_launch(void* const* d_in, const int* in_sizes, int n_in,
                              void* d_out, int out_size) {
    const float* x     = (const float*)d_in[0];
    const float* gamma = (const float*)d_in[1];
    const float* beta  = (const float*)d_in[2];
    const float* wq    = (const float*)d_in[3];
    const float* bq    = (const float*)d_in[4];
    const float* wk    = (const float*)d_in[5];
    const float* bk    = (const float*)d_in[6];
    const float* wv    = (const float*)d_in[7];
    const float* bv    = (const float*)d_in[8];
    const float* wo    = (const float*)d_in[9];
    const float* bo    = (const float*)d_in[10];
    float* out = (float*)d_out;

    float *hn, *q, *k, *vt, *o, *S, *w;
    cudaGetSymbolAddress((void**)&hn, g_hn);
    cudaGetSymbolAddress((void**)&q,  g_q);
    cudaGetSymbolAddress((void**)&k,  g_k);
    cudaGetSymbolAddress((void**)&vt, g_vt);
    cudaGetSymbolAddress((void**)&o,  g_o);
    cudaGetSymbolAddress((void**)&S,  g_S);
    cudaGetSymbolAddress((void**)&w,  g_w);

    const long long P  = (long long)CH * NPIX;     // 2097152
    const long long PS = (long long)NPIX * NPIX;   // 16777216
    const float scale  = 0.044194173824159216f;    // 512^-0.5
    const int WN  = CH * CH;                       // 262144
    const int DYN = STAGES * 16384;                // 65536 bytes

    cudaFuncSetAttribute(gemm_tf32, cudaFuncAttributeMaxDynamicSharedMemorySize, DYN);

    gn_stats<<<BATCH * GROUPS, 256>>>(x);
    gn_apply_t<<<dim3(NPIX / 32, CH / 32, BATCH), dim3(32, 8)>>>(x, gamma, beta);

    cvt_w<<<WN / 1024, 256>>>(wq, w + 0 * WN);
    cvt_w<<<WN / 1024, 256>>>(wk, w + 1 * WN);
    cvt_w<<<WN / 1024, 256>>>(wv, w + 2 * WN);
    cvt_w<<<WN / 1024, 256>>>(wo, w + 3 * WN);

    // q[n][c] = hnT[n][:] . Wq[c][:] + bq[c]   (M=4096, N=512, K=512)
    gemm_tf32<<<dim3(4, 32, BATCH), 256, DYN>>>(
        hn, w + 0 * WN, q, CH, CH, CH, CH, P, 0, P, 1.f, bq, 2, 1, nullptr, 0);
    gemm_tf32<<<dim3(4, 32, BATCH), 256, DYN>>>(
        hn, w + 1 * WN, k, CH, CH, CH, CH, P, 0, P, 1.f, bk, 2, 1, nullptr, 0);
    // vT[c][n] = Wv[c][:] . hnT[n][:] + bv[c]  (M=512, N=4096, K=512)
    gemm_tf32<<<dim3(32, 4, BATCH), 256, DYN>>>(
        w + 2 * WN, hn, vt, CH, CH, CH, NPIX, 0, P, P, 1.f, bv, 1, 1, nullptr, 0);

    // S[i][j] = scale * q[i][:] . k[j][:]      (M=N=4096, K=512), fp32 out
    gemm_tf32<<<dim3(32, 32, BATCH), 256, DYN>>>(
        q, k, S, CH, CH, CH, NPIX, P, P, PS, scale, nullptr, 0, 0, nullptr, 0);

    softmax_rows<<<BATCH * NPIX, 256>>>(S);

    // O[i][c] = P[i][:] . vT[c][:]             (M=4096, N=512, K=4096), tf32 out
    gemm_tf32<<<dim3(4, 32, BATCH), 256, DYN>>>(
        S, vt, o, NPIX, NPIX, NPIX, CH, PS, P, P, 1.f, nullptr, 0, 1, nullptr, 0);

    // out[c][n] = Wo[c][:] . O[n][:] + bo[c] + x[c][n]  (M=512, N=4096, K=512)
    gemm_tf32<<<dim3(32, 4, BATCH), 256, DYN>>>(
        w + 3 * WN, o, out, CH, CH, CH, NPIX, 0, P, P, 1.f, bo, 1, 0, x, P);
}

// round 7
// speedup vs baseline: 2.4561x; 1.1572x over previous
#include <cuda_runtime.h>
#include <math.h>
#include <stdint.h>

#define CH     512
#define NPIX   4096
#define BATCH  4
#define GROUPS 32
#define STAGES 4

#define PELEM  ((size_t)BATCH * NPIX * CH)        // 8388608
#define SELEM  ((size_t)BATCH * NPIX * NPIX)      // 67108864

// ---------------- scratch (device globals: allocation-guard safe) ----------
__device__ float g_hn[PELEM];    // hn^T [b][n][c]  (tf32-rounded)
__device__ float g_q [PELEM];    // q    [b][n][c]  (tf32)
__device__ float g_k [PELEM];    // k    [b][n][c]  (tf32)
__device__ float g_vt[PELEM];    // v^T  [b][c][n]  (tf32)
__device__ float g_o [PELEM];    // O    [b][n][c]  (tf32)
__device__ float g_S [SELEM];    // S logits fp32 / probs tf32
__device__ float g_w [4 * CH * CH];  // tf32 copies of wq,wk,wv,wo
__device__ float g_mean[BATCH * GROUPS];
__device__ float g_rstd[BATCH * GROUPS];

// ---------------- helpers ---------------------------------------------------
__device__ __forceinline__ float f2tf(float x) {
    uint32_t r;
    asm("cvt.rna.tf32.f32 %0, %1;" : "=r"(r) : "f"(x));
    return __uint_as_float(r);
}
__device__ __forceinline__ uint32_t smem_u32(const void* p) {
    uint32_t a;
    asm("{ .reg .u64 t; cvta.to.shared.u64 t, %1; cvt.u32.u64 %0, t; }"
        : "=r"(a) : "l"(p));
    return a;
}
__device__ __forceinline__ void cp16(uint32_t dst, const float* src) {
    asm volatile("cp.async.cg.shared.global [%0], [%1], 16;" :: "r"(dst), "l"(src));
}
__device__ __forceinline__ void ldsm4(uint32_t* r, uint32_t addr) {
    asm volatile("ldmatrix.sync.aligned.m8n8.x4.shared.b16 {%0,%1,%2,%3}, [%4];"
                 : "=r"(r[0]), "=r"(r[1]), "=r"(r[2]), "=r"(r[3]) : "r"(addr));
}
__device__ __forceinline__ void mma_tf32(float* d, const uint32_t* a, const uint32_t* b) {
    asm volatile(
        "mma.sync.aligned.m16n8k8.row.col.f32.tf32.tf32.f32 "
        "{%0,%1,%2,%3}, {%4,%5,%6,%7}, {%8,%9}, {%0,%1,%2,%3};\n"
        : "+f"(d[0]), "+f"(d[1]), "+f"(d[2]), "+f"(d[3])
        : "r"(a[0]), "r"(a[1]), "r"(a[2]), "r"(a[3]), "r"(b[0]), "r"(b[1]));
}

// ---------------- GroupNorm ------------------------------------------------
__global__ void gn_stats(const float* __restrict__ x) {
    int bg = blockIdx.x;   // b*32+g; group = 16 contiguous channels
    const float4* p = (const float4*)(x + (long long)bg * 16 * NPIX);
    float s = 0.f, sq = 0.f;
    for (int i = threadIdx.x; i < 16 * NPIX / 4; i += blockDim.x) {
        float4 v = p[i];
        s  += v.x + v.y + v.z + v.w;
        sq += v.x*v.x + v.y*v.y + v.z*v.z + v.w*v.w;
    }
    __shared__ float sh_s[8], sh_q[8];
    #pragma unroll
    for (int o = 16; o; o >>= 1) {
        s  += __shfl_xor_sync(0xffffffffu, s,  o);
        sq += __shfl_xor_sync(0xffffffffu, sq, o);
    }
    if ((threadIdx.x & 31) == 0) { sh_s[threadIdx.x >> 5] = s; sh_q[threadIdx.x >> 5] = sq; }
    __syncthreads();
    if (threadIdx.x == 0) {
        float ts = 0.f, tq = 0.f;
        #pragma unroll
        for (int i = 0; i < 8; i++) { ts += sh_s[i]; tq += sh_q[i]; }
        const float inv = 1.f / (float)(16 * NPIX);
        float m   = ts * inv;
        float var = tq * inv - m * m;
        g_mean[bg] = m;
        g_rstd[bg] = rsqrtf(var + 1e-6f);
    }
}

// GroupNorm apply + transpose + tf32 round: x[b][c][n] -> hnT[b][n][c]
__global__ void gn_apply_t(const float* __restrict__ x,
                           const float* __restrict__ gamma,
                           const float* __restrict__ beta) {
    __shared__ float tile[32][33];
    int b = blockIdx.z, c0 = blockIdx.y * 32, n0 = blockIdx.x * 32;
    int tx = threadIdx.x, ty = threadIdx.y;   // (32, 8)
    const float* xb = x + ((long long)b * CH + c0) * NPIX;
    #pragma unroll
    for (int i = 0; i < 4; i++)
        tile[ty + 8*i][tx] = xb[(long long)(ty + 8*i) * NPIX + n0 + tx];
    __syncthreads();
    int c  = c0 + tx;
    int bg = b * GROUPS + (c >> 4);
    float ga = gamma[c] * g_rstd[bg];
    float be = beta[c] - g_mean[bg] * ga;
    #pragma unroll
    for (int i = 0; i < 4; i++) {
        int n = n0 + ty + 8*i;
        g_hn[((long long)b * NPIX + n) * CH + c] = f2tf(tile[tx][ty + 8*i] * ga + be);
    }
}

// ---------------- weight tf32 copy -----------------------------------------
__global__ void cvt_w(const float* __restrict__ w, float* __restrict__ o) {
    int i = blockIdx.x * blockDim.x + threadIdx.x;
    float4 v = ((const float4*)w)[i];
    float4 r;
    r.x = f2tf(v.x); r.y = f2tf(v.y); r.z = f2tf(v.z); r.w = f2tf(v.w);
    ((float4*)o)[i] = r;
}

// ---------------- tf32 tensor-core GEMM, cp.async pipeline + ldmatrix ------
// C[m][n] = alpha * sum_k A[m][k]*B[n][k] (+bias) (+resid)
// Both operands K-contiguous, already tf32-rounded.
// smem layout per stage: word(row,k) = row*16 + (((k>>2)^((row>>1)&3))*4 + (k&3))

__global__ void __launch_bounds__(256, 2)
gemm_tf32(const float* __restrict__ Ag, const float* __restrict__ Bg,
          float* __restrict__ Cg,
          int K, int lda, int ldb, int ldc,
          long long sA, long long sB, long long sC,
          float alpha, const float* __restrict__ bias, int bmode, int cvtout,
          const float* __restrict__ resid, long long sR)
{
    extern __shared__ float sm[];   // STAGES * 4096 floats (A 2048 | B 2048)
    const uint32_t smb = smem_u32(sm);

    const int t = threadIdx.x, lane = t & 31, warp = t >> 5;
    const int wm = warp >> 2, wn = warp & 3;        // 2 x 4 warp grid, 64x32 tiles
    const int fr = lane >> 2, fc = lane & 3;
    const int bi = blockIdx.y * 128, bn = blockIdx.x * 128, bz = blockIdx.z;

    const float* A = Ag + bz * sA;
    const float* B = Bg + bz * sB;

    // copy geometry: idx = t + 256*i over 512 16B-chunks per operand
    const int crow0 = t >> 2, cc4 = t & 3;

    // ldmatrix per-lane geometry
    const int arow = wm * 64 + (lane & 15);          // A row (mi adds 16s)
    const int pa   = (arow >> 1) & 3;                // swizzle phase (mi-invariant)
    const int ha   = (lane >> 4) & 1;                // k-chunk select bit
    const int brow = wn * 32 + (lane & 7) + ((lane & 16) ? 8 : 0);
    const int pb   = (brow >> 1) & 3;
    const int hb   = (lane >> 3) & 1;

    float acc[4][4][4];
    #pragma unroll
    for (int mi = 0; mi < 4; mi++)
        #pragma unroll
        for (int ni = 0; ni < 4; ni++)
            #pragma unroll
            for (int q = 0; q < 4; q++) acc[mi][ni][q] = 0.f;

    const int nk = K >> 4;

    auto ISSUE = [&](int ch, int slot) {
        const int k0 = ch << 4;
        const uint32_t sbase = smb + (uint32_t)slot * 16384u;
        #pragma unroll
        for (int i = 0; i < 2; i++) {
            int row = crow0 + 64 * i;
            int chp = cc4 ^ ((row >> 1) & 3);
            uint32_t off = (uint32_t)(row * 16 + chp * 4) * 4u;
            cp16(sbase + off,          A + (long long)(bi + row) * lda + k0 + 4 * cc4);
            cp16(sbase + 8192u + off,  B + (long long)(bn + row) * ldb + k0 + 4 * cc4);
        }
    };
    auto COMPUTE = [&](int slot) {
        const uint32_t sbase = smb + (uint32_t)slot * 16384u;
        #pragma unroll
        for (int s = 0; s < 2; s++) {
            uint32_t af[4][4], bf[2][4];
            const uint32_t ca = (uint32_t)(((2 * s + ha) ^ pa) * 16);
            const uint32_t cb = (uint32_t)(((2 * s + hb) ^ pb) * 16);
            #pragma unroll
            for (int mi = 0; mi < 4; mi++)
                ldsm4(af[mi], sbase + (uint32_t)((arow + mi * 16) * 64) + ca);
            #pragma unroll
            for (int p = 0; p < 2; p++)
                ldsm4(bf[p], sbase + 8192u + (uint32_t)((brow + p * 16) * 64) + cb);
            #pragma unroll
            for (int mi = 0; mi < 4; mi++)
                #pragma unroll
                for (int ni = 0; ni < 4; ni++)
                    mma_tf32(acc[mi][ni], af[mi], &bf[ni >> 1][2 * (ni & 1)]);
        }
    };

    // prologue: fill STAGES-1 stages
    #pragma unroll
    for (int p = 0; p < STAGES - 1; p++) {
        ISSUE(p, p);
        asm volatile("cp.async.commit_group;" ::: "memory");
    }

    for (int ch = 0; ch < nk; ch++) {
        asm volatile("cp.async.wait_group %0;" :: "n"(STAGES - 2) : "memory");
        __syncthreads();
        if (ch + STAGES - 1 < nk) ISSUE(ch + STAGES - 1, (ch + STAGES - 1) & (STAGES - 1));
        asm volatile("cp.async.commit_group;" ::: "memory");
        COMPUTE(ch & (STAGES - 1));
    }

    // -------- epilogue -----------------------------------------------------
    float* C = Cg + bz * sC;
    #pragma unroll
    for (int mi = 0; mi < 4; mi++) {
        int row = bi + wm * 64 + mi * 16 + fr;
        float bv0 = 0.f, bv1 = 0.f;
        if (bmode == 1) { bv0 = bias[row]; bv1 = bias[row + 8]; }
        #pragma unroll
        for (int ni = 0; ni < 4; ni++) {
            int col = bn + wn * 32 + ni * 8 + 2 * fc;
            float2 o0, o1;
            o0.x = acc[mi][ni][0] * alpha; o0.y = acc[mi][ni][1] * alpha;
            o1.x = acc[mi][ni][2] * alpha; o1.y = acc[mi][ni][3] * alpha;
            if (bmode == 1) {
                o0.x += bv0; o0.y += bv0; o1.x += bv1; o1.y += bv1;
            } else if (bmode == 2) {
                float2 bb = *(const float2*)(bias + col);
                o0.x += bb.x; o0.y += bb.y; o1.x += bb.x; o1.y += bb.y;
            }
            if (resid) {
                const float* R = resid + bz * sR;
                float2 r0 = *(const float2*)(R + (long long)row * ldc + col);
                float2 r1 = *(const float2*)(R + (long long)(row + 8) * ldc + col);
                o0.x += r0.x; o0.y += r0.y; o1.x += r1.x; o1.y += r1.y;
            }
            if (cvtout) {
                o0.x = f2tf(o0.x); o0.y = f2tf(o0.y);
                o1.x = f2tf(o1.x); o1.y = f2tf(o1.y);
            }
            *(float2*)(C + (long long)row * ldc + col)       = o0;
            *(float2*)(C + (long long)(row + 8) * ldc + col) = o1;
        }
    }
}

// ---------------- row softmax (4096 per row; tf32-rounded output) ----------
__global__ void softmax_rows(float* __restrict__ S) {
    float* p = S + (long long)blockIdx.x * NPIX;
    const int t = threadIdx.x;
    float4 v[4];
    float mx = -1e30f;
    #pragma unroll
    for (int j = 0; j < 4; j++) {
        v[j] = ((const float4*)p)[t + j * 256];
        mx = fmaxf(mx, fmaxf(fmaxf(v[j].x, v[j].y), fmaxf(v[j].z, v[j].w)));
    }
    __shared__ float shm[8], shs[8];
    #pragma unroll
    for (int o = 16; o; o >>= 1) mx = fmaxf(mx, __shfl_xor_sync(0xffffffffu, mx, o));
    if ((t & 31) == 0) shm[t >> 5] = mx;
    __syncthreads();
    mx = shm[0];
    #pragma unroll
    for (int i = 1; i < 8; i++) mx = fmaxf(mx, shm[i]);

    float s = 0.f;
    #pragma unroll
    for (int j = 0; j < 4; j++) {
        v[j].x = __expf(v[j].x - mx); v[j].y = __expf(v[j].y - mx);
        v[j].z = __expf(v[j].z - mx); v[j].w = __expf(v[j].w - mx);
        s += v[j].x + v[j].y + v[j].z + v[j].w;
    }
    #pragma unroll
    for (int o = 16; o; o >>= 1) s += __shfl_xor_sync(0xffffffffu, s, o);
    if ((t & 31) == 0) shs[t >> 5] = s;
    __syncthreads();
    s = 0.f;
    #pragma unroll
    for (int i = 0; i < 8; i++) s += shs[i];
    float inv = 1.f / s;
    #pragma unroll
    for (int j = 0; j < 4; j++) {
        v[j].x = f2tf(v[j].x * inv); v[j].y = f2tf(v[j].y * inv);
        v[j].z = f2tf(v[j].z * inv); v[j].w = f2tf(v[j].w * inv);
        ((float4*)p)[t + j * 256] = v[j];
    }
}

// ---------------- launch ---------------------------------------------------
extern "C" void kernel_launch(void* const* d_in, const int* in_sizes, int n_in,
                              void* d_out, int out_size) {
    const float* x     = (const float*)d_in[0];
    const float* gamma = (const float*)d_in[1];
    const float* beta  = (const float*)d_in[2];
    const float* wq    = (const float*)d_in[3];
    const float* bq    = (const float*)d_in[4];
    const float* wk    = (const float*)d_in[5];
    const float* bk    = (const float*)d_in[6];
    const float* wv    = (const float*)d_in[7];
    const float* bv    = (const float*)d_in[8];
    const float* wo    = (const float*)d_in[9];
    const float* bo    = (const float*)d_in[10];
    float* out = (float*)d_out;

    float *hn, *q, *k, *vt, *o, *S, *w;
    cudaGetSymbolAddress((void**)&hn, g_hn);
    cudaGetSymbolAddress((void**)&q,  g_q);
    cudaGetSymbolAddress((void**)&k,  g_k);
    cudaGetSymbolAddress((void**)&vt, g_vt);
    cudaGetSymbolAddress((void**)&o,  g_o);
    cudaGetSymbolAddress((void**)&S,  g_S);
    cudaGetSymbolAddress((void**)&w,  g_w);

    const long long P  = (long long)CH * NPIX;     // 2097152
    const long long PS = (long long)NPIX * NPIX;   // 16777216
    const float scale  = 0.044194173824159216f;    // 512^-0.5
    const int WN  = CH * CH;                       // 262144
    const int DYN = STAGES * 16384;                // 65536 bytes

    cudaFuncSetAttribute(gemm_tf32, cudaFuncAttributeMaxDynamicSharedMemorySize, DYN);

    gn_stats<<<BATCH * GROUPS, 256>>>(x);
    gn_apply_t<<<dim3(NPIX / 32, CH / 32, BATCH), dim3(32, 8)>>>(x, gamma, beta);

    cvt_w<<<WN / 1024, 256>>>(wq, w + 0 * WN);
    cvt_w<<<WN / 1024, 256>>>(wk, w + 1 * WN);
    cvt_w<<<WN / 1024, 256>>>(wv, w + 2 * WN);
    cvt_w<<<WN / 1024, 256>>>(wo, w + 3 * WN);

    // q[n][c] = hnT[n][:] . Wq[c][:] + bq[c]   (M=4096, N=512, K=512)
    gemm_tf32<<<dim3(4, 32, BATCH), 256, DYN>>>(
        hn, w + 0 * WN, q, CH, CH, CH, CH, P, 0, P, 1.f, bq, 2, 1, nullptr, 0);
    gemm_tf32<<<dim3(4, 32, BATCH), 256, DYN>>>(
        hn, w + 1 * WN, k, CH, CH, CH, CH, P, 0, P, 1.f, bk, 2, 1, nullptr, 0);
    // vT[c][n] = Wv[c][:] . hnT[n][:] + bv[c]  (M=512, N=4096, K=512)
    gemm_tf32<<<dim3(32, 4, BATCH), 256, DYN>>>(
        w + 2 * WN, hn, vt, CH, CH, CH, NPIX, 0, P, P, 1.f, bv, 1, 1, nullptr, 0);

    // S[i][j] = scale * q[i][:] . k[j][:]      (M=N=4096, K=512), fp32 out
    gemm_tf32<<<dim3(32, 32, BATCH), 256, DYN>>>(
        q, k, S, CH, CH, CH, NPIX, P, P, PS, scale, nullptr, 0, 0, nullptr, 0);

    softmax_rows<<<BATCH * NPIX, 256>>>(S);

    // O[i][c] = P[i][:] . vT[c][:]             (M=4096, N=512, K=4096), tf32 out
    gemm_tf32<<<dim3(4, 32, BATCH), 256, DYN>>>(
        S, vt, o, NPIX, NPIX, NPIX, CH, PS, P, P, 1.f, nullptr, 0, 1, nullptr, 0);

    // out[c][n] = Wo[c][:] . O[n][:] + bo[c] + x[c][n]  (M=512, N=4096, K=512)
    gemm_tf32<<<dim3(32, 4, BATCH), 256, DYN>>>(
        w + 3 * WN, o, out, CH, CH, CH, NPIX, 0, P, P, 1.f, bo, 1, 0, x, P);
}